// round 2
// baseline (speedup 1.0000x reference)
#include <cuda_runtime.h>
#include <math.h>

#define B_  4
#define T_  2048
#define C_  1024
#define H_  16
#define Dh_ 64
#define KQV_COLS (3 * C_)   // 3072

static_assert((B_ * T_) % 128 == 0, "M tile");
static_assert(KQV_COLS % 128 == 0 && C_ % 128 == 0, "N tile");
static_assert(C_ % 8 == 0, "K tile");
static_assert(Dh_ == 64 && H_ * Dh_ == C_, "head geometry");

// Scratch (allocation-free rule: __device__ globals)
__device__ float g_kqv [(size_t)B_ * T_ * KQV_COLS]; // (B*T, 3C): col = s*1024 + h*64 + d, s=0:k 1:q 2:v
__device__ float g_attn[(size_t)B_ * T_ * C_];       // (B*T, C):  col = h*64 + d

// ---------------------------------------------------------------------------
// SIMT fp32 GEMM: C[M,N] = A[M,K] @ B[K,N], all row-major.
// 128x128 block tile, BK=8, 256 threads, 8x8 per-thread microtile.
// ---------------------------------------------------------------------------
__global__ __launch_bounds__(256) void sgemm_kernel(
    const float* __restrict__ A, const float* __restrict__ B,
    float* __restrict__ C, int M, int N, int K)
{
    __shared__ float As[8][132];   // transposed, +4 pad kills store conflicts
    __shared__ float Bs[8][128];

    const int tid = threadIdx.x;
    const int tx  = tid & 15;      // 0..15 -> 8 output cols each
    const int ty  = tid >> 4;      // 0..15 -> 8 output rows each
    const int m0  = blockIdx.y * 128;
    const int n0  = blockIdx.x * 128;

    const int arow = tid >> 1;            // 0..127
    const int acol = (tid & 1) * 4;       // 0 or 4
    const int brow = tid >> 5;            // 0..7
    const int bcol = (tid & 31) * 4;      // 0..124

    const float* Aptr = A + (size_t)(m0 + arow) * K + acol;
    const float* Bptr = B + (size_t)brow * N + n0 + bcol;

    float acc[8][8];
    #pragma unroll
    for (int i = 0; i < 8; i++)
        #pragma unroll
        for (int j = 0; j < 8; j++) acc[i][j] = 0.f;

    for (int k0 = 0; k0 < K; k0 += 8) {
        float4 a4 = *(const float4*)(Aptr + k0);
        float4 b4 = *(const float4*)(Bptr + (size_t)k0 * N);
        __syncthreads();                         // previous tile fully consumed
        As[acol + 0][arow] = a4.x;
        As[acol + 1][arow] = a4.y;
        As[acol + 2][arow] = a4.z;
        As[acol + 3][arow] = a4.w;
        *(float4*)&Bs[brow][bcol] = b4;
        __syncthreads();

        #pragma unroll
        for (int kk = 0; kk < 8; kk++) {
            float4 a0 = *(const float4*)&As[kk][ty * 8];
            float4 a1 = *(const float4*)&As[kk][ty * 8 + 4];
            float4 b0 = *(const float4*)&Bs[kk][tx * 8];
            float4 b1 = *(const float4*)&Bs[kk][tx * 8 + 4];
            float ar[8] = {a0.x, a0.y, a0.z, a0.w, a1.x, a1.y, a1.z, a1.w};
            float br[8] = {b0.x, b0.y, b0.z, b0.w, b1.x, b1.y, b1.z, b1.w};
            #pragma unroll
            for (int i = 0; i < 8; i++)
                #pragma unroll
                for (int j = 0; j < 8; j++)
                    acc[i][j] += ar[i] * br[j];
        }
    }

    #pragma unroll
    for (int i = 0; i < 8; i++) {
        float* crow = C + (size_t)(m0 + ty * 8 + i) * N + n0 + tx * 8;
        *(float4*)(crow)     = make_float4(acc[i][0], acc[i][1], acc[i][2], acc[i][3]);
        *(float4*)(crow + 4) = make_float4(acc[i][4], acc[i][5], acc[i][6], acc[i][7]);
    }
}

// ---------------------------------------------------------------------------
// Flash attention, fp32. One CTA = 64 queries of one (b,h). Bk = 32 keys/tile.
// Q stored d-major (Qt[d][q], scaled by dk), K stored d-major (Kt[d][k]);
// P (post-softmax) overwrites the K buffer. Softmax running state (m,l) in
// registers, reduced with __shfl_xor across the 16 tx lanes sharing a row.
// ---------------------------------------------------------------------------
__global__ __launch_bounds__(256) void flash_kernel()
{
    __shared__ float Qt[64 * 64];   // Qt[d*64 + q]           16 KB
    __shared__ float KP[64 * 36];   // Kt[d*36 + k] OR Pt[k*68 + q]  (2304 >= 2176)
    __shared__ float Vs[32 * 64];   // Vs[k*64 + d]            8 KB

    const int tid = threadIdx.x;
    const int tx  = tid & 15;       // 0..15: 2 key-cols (S) / 4 d-cols (O)
    const int ty  = tid >> 4;       // 0..15: 4 query rows
    const int bh  = blockIdx.y;
    const int b   = bh >> 4, h = bh & 15;
    const int q0  = blockIdx.x * 64;

    const float* Kbase = g_kqv + (size_t)b * T_ * KQV_COLS + h * Dh_;           // s=0
    const float* Qbase = Kbase + C_;                                             // s=1
    const float* Vbase = Kbase + 2 * C_;                                         // s=2

    // Fill Qt (transposed, pre-scaled by dk = 1/8)
    #pragma unroll
    for (int it = 0; it < 4; it++) {
        int fid = tid + it * 256;           // 0..1023
        int q   = fid >> 4;
        int dg  = (fid & 15) * 4;
        float4 v = *(const float4*)(Qbase + (size_t)(q0 + q) * KQV_COLS + dg);
        Qt[(dg + 0) * 64 + q] = v.x * 0.125f;
        Qt[(dg + 1) * 64 + q] = v.y * 0.125f;
        Qt[(dg + 2) * 64 + q] = v.z * 0.125f;
        Qt[(dg + 3) * 64 + q] = v.w * 0.125f;
    }

    float o[4][4];
    float mi[4], li[4];
    #pragma unroll
    for (int i = 0; i < 4; i++) {
        mi[i] = -1e30f; li[i] = 0.f;
        #pragma unroll
        for (int j = 0; j < 4; j++) o[i][j] = 0.f;
    }

    for (int t = 0; t < T_ / 32; t++) {
        const int j0 = t * 32;
        __syncthreads();   // prior PV done (and Qt visible on t==0)

        // Load K (transposed) and V tiles
        #pragma unroll
        for (int it = 0; it < 2; it++) {
            int fid = tid + it * 256;       // 0..511
            int kr  = fid >> 4;             // 0..31
            int dg  = (fid & 15) * 4;
            float4 kv = *(const float4*)(Kbase + (size_t)(j0 + kr) * KQV_COLS + dg);
            KP[(dg + 0) * 36 + kr] = kv.x;
            KP[(dg + 1) * 36 + kr] = kv.y;
            KP[(dg + 2) * 36 + kr] = kv.z;
            KP[(dg + 3) * 36 + kr] = kv.w;
            float4 vv = *(const float4*)(Vbase + (size_t)(j0 + kr) * KQV_COLS + dg);
            *(float4*)&Vs[kr * 64 + dg] = vv;
        }
        __syncthreads();

        // S[4 rows][2 cols] = (Q dk) . K
        float s[4][2];
        #pragma unroll
        for (int i = 0; i < 4; i++) { s[i][0] = 0.f; s[i][1] = 0.f; }
        #pragma unroll 16
        for (int d = 0; d < 64; d++) {
            float4 a  = *(const float4*)&Qt[d * 64 + ty * 4];
            float2 bk = *(const float2*)&KP[d * 36 + tx * 2];
            s[0][0] += a.x * bk.x;  s[0][1] += a.x * bk.y;
            s[1][0] += a.y * bk.x;  s[1][1] += a.y * bk.y;
            s[2][0] += a.z * bk.x;  s[2][1] += a.z * bk.y;
            s[3][0] += a.w * bk.x;  s[3][1] += a.w * bk.y;
        }

        // Online softmax (register state, shuffle reductions over tx lanes)
        float p[4][2], sc4[4];
        #pragma unroll
        for (int i = 0; i < 4; i++) {
            float rm = fmaxf(s[i][0], s[i][1]);
            #pragma unroll
            for (int off = 8; off; off >>= 1)
                rm = fmaxf(rm, __shfl_xor_sync(0xffffffffu, rm, off));
            float mnew = fmaxf(mi[i], rm);
            float scl  = __expf(mi[i] - mnew);
            p[i][0] = __expf(s[i][0] - mnew);
            p[i][1] = __expf(s[i][1] - mnew);
            float rs = p[i][0] + p[i][1];
            #pragma unroll
            for (int off = 8; off; off >>= 1)
                rs += __shfl_xor_sync(0xffffffffu, rs, off);
            li[i] = li[i] * scl + rs;
            mi[i] = mnew;
            sc4[i] = scl;
        }
        __syncthreads();   // all done reading Kt -> safe to overwrite with Pt

        // Store Pt[k][q] (float4 over the 4 contiguous q's), rescale O
        #pragma unroll
        for (int j = 0; j < 2; j++) {
            *(float4*)&KP[(tx * 2 + j) * 68 + ty * 4] =
                make_float4(p[0][j], p[1][j], p[2][j], p[3][j]);
        }
        #pragma unroll
        for (int i = 0; i < 4; i++)
            #pragma unroll
            for (int j = 0; j < 4; j++) o[i][j] *= sc4[i];
        __syncthreads();   // Pt visible

        // O += P @ V
        #pragma unroll 8
        for (int k = 0; k < 32; k++) {
            float4 pp = *(const float4*)&KP[k * 68 + ty * 4];
            float4 vv = *(const float4*)&Vs[k * 64 + tx * 4];
            o[0][0] += pp.x * vv.x; o[0][1] += pp.x * vv.y; o[0][2] += pp.x * vv.z; o[0][3] += pp.x * vv.w;
            o[1][0] += pp.y * vv.x; o[1][1] += pp.y * vv.y; o[1][2] += pp.y * vv.z; o[1][3] += pp.y * vv.w;
            o[2][0] += pp.z * vv.x; o[2][1] += pp.z * vv.y; o[2][2] += pp.z * vv.z; o[2][3] += pp.z * vv.w;
            o[3][0] += pp.w * vv.x; o[3][1] += pp.w * vv.y; o[3][2] += pp.w * vv.z; o[3][3] += pp.w * vv.w;
        }
    }

    // Epilogue: divide by l, write (B*T, C) with col = h*64 + d
    float* Obase = g_attn + (size_t)b * T_ * C_ + h * Dh_;
    #pragma unroll
    for (int i = 0; i < 4; i++) {
        float inv = 1.0f / li[i];
        *(float4*)&Obase[(size_t)(q0 + ty * 4 + i) * C_ + tx * 4] =
            make_float4(o[i][0] * inv, o[i][1] * inv, o[i][2] * inv, o[i][3] * inv);
    }
}

// ---------------------------------------------------------------------------
extern "C" void kernel_launch(void* const* d_in, const int* in_sizes, int n_in,
                              void* d_out, int out_size)
{
    const float* x     = (const float*)d_in[0];   // (4,2048,1024)
    const float* Wkqv  = (const float*)d_in[1];   // (1024,3072)
    const float* Wproj = (const float*)d_in[2];   // (1024,1024)
    float* out = (float*)d_out;

    // One-time scratch address resolution (non-stream API; cached so the
    // captured call sequence is kernel launches only).
    static float* kqv_ptr  = nullptr;
    static float* attn_ptr = nullptr;
    if (!kqv_ptr) {
        cudaGetSymbolAddress((void**)&kqv_ptr,  g_kqv);
        cudaGetSymbolAddress((void**)&attn_ptr, g_attn);
    }

    const int M = B_ * T_;   // 8192

    // 1) KQV projection: (8192,1024) @ (1024,3072)
    sgemm_kernel<<<dim3(KQV_COLS / 128, M / 128), 256>>>(x, Wkqv, kqv_ptr, M, KQV_COLS, C_);
    // 2) Flash attention over 64 (b,h) pairs
    flash_kernel<<<dim3(T_ / 64, B_ * H_), 256>>>();
    // 3) Output projection: (8192,1024) @ (1024,1024)
    sgemm_kernel<<<dim3(C_ / 128, M / 128), 256>>>(attn_ptr, Wproj, out, M, C_, C_);
}

// round 6
// speedup vs baseline: 1.3774x; 1.3774x over previous
#include <cuda_runtime.h>
#include <cuda_bf16.h>
#include <cstdint>
#include <math.h>

#define B_  4
#define T_  2048
#define C_  1024
#define H_  16
#define Dh_ 64
#define KQV_COLS (3 * C_)   // 3072
#define M_  (B_ * T_)       // 8192

static_assert(Dh_ == 64 && H_ * Dh_ == C_, "head geometry");

// ---------------------------------------------------------------------------
// Device scratch (allocation-free rule: __device__ globals)
// ---------------------------------------------------------------------------
__device__ __align__(16) float         g_kqv [(size_t)M_ * KQV_COLS]; // (B*T,3C) fp32
__device__ __align__(16) __nv_bfloat16 g_xhi [(size_t)M_ * C_];
__device__ __align__(16) __nv_bfloat16 g_xlo [(size_t)M_ * C_];
__device__ __align__(16) __nv_bfloat16 g_wkhi[(size_t)KQV_COLS * C_]; // [N,K]
__device__ __align__(16) __nv_bfloat16 g_wklo[(size_t)KQV_COLS * C_];
__device__ __align__(16) __nv_bfloat16 g_wphi[(size_t)C_ * C_];       // [N,K]
__device__ __align__(16) __nv_bfloat16 g_wplo[(size_t)C_ * C_];
__device__ __align__(16) __nv_bfloat16 g_ahi [(size_t)M_ * C_];       // attn out hi
__device__ __align__(16) __nv_bfloat16 g_alo [(size_t)M_ * C_];       // attn out lo

// ---------------------------------------------------------------------------
// PTX helpers: ldmatrix / mma.sync / cp.async (all legal on compute_103)
// ---------------------------------------------------------------------------
__device__ __forceinline__ uint32_t smem_u32(const void* p) {
    uint32_t a;
    asm("{ .reg .u64 t; cvta.to.shared.u64 t, %1; cvt.u32.u64 %0, t; }" : "=r"(a) : "l"(p));
    return a;
}
#define LDSM4(r0, r1, r2, r3, addr) \
    asm volatile("ldmatrix.sync.aligned.m8n8.x4.shared.b16 {%0,%1,%2,%3}, [%4];" \
        : "=r"(r0), "=r"(r1), "=r"(r2), "=r"(r3) : "r"(addr))
#define MMA16816(d, a, b) \
    asm volatile("mma.sync.aligned.m16n8k16.row.col.f32.bf16.bf16.f32 " \
        "{%0,%1,%2,%3}, {%4,%5,%6,%7}, {%8,%9}, {%0,%1,%2,%3};" \
        : "+f"((d)[0]), "+f"((d)[1]), "+f"((d)[2]), "+f"((d)[3]) \
        : "r"((a)[0]), "r"((a)[1]), "r"((a)[2]), "r"((a)[3]), \
          "r"((b)[0]), "r"((b)[1]))
#define CP_ASYNC16(sdst, gsrc) \
    asm volatile("cp.async.cg.shared.global [%0], [%1], 16;" :: "r"(sdst), "l"(gsrc))
#define CP_COMMIT() asm volatile("cp.async.commit_group;" ::: "memory")
#define CP_WAIT(n)  asm volatile("cp.async.wait_group %0;" :: "n"(n) : "memory")

__device__ __forceinline__ uint32_t pack_bf(__nv_bfloat16 a, __nv_bfloat16 b) {
    return ((uint32_t)__bfloat16_as_ushort(b) << 16) | (uint32_t)__bfloat16_as_ushort(a);
}

// ---------------------------------------------------------------------------
// Prep: x fp32 -> (hi,lo) bf16, elementwise.
// ---------------------------------------------------------------------------
__global__ __launch_bounds__(256) void prep_a_kernel(
    const float4* __restrict__ X, uint2* __restrict__ Hi, uint2* __restrict__ Lo)
{
    int idx = blockIdx.x * 256 + threadIdx.x;
    float4 v = X[idx];
    __nv_bfloat16 hx = __float2bfloat16(v.x), hy = __float2bfloat16(v.y);
    __nv_bfloat16 hz = __float2bfloat16(v.z), hw = __float2bfloat16(v.w);
    uint2 Hh; Hh.x = pack_bf(hx, hy); Hh.y = pack_bf(hz, hw);
    float rx = v.x - __bfloat162float(hx), ry = v.y - __bfloat162float(hy);
    float rz = v.z - __bfloat162float(hz), rw = v.w - __bfloat162float(hw);
    uint2 Ll; Ll.x = pack_bf(__float2bfloat16(rx), __float2bfloat16(ry));
    Ll.y = pack_bf(__float2bfloat16(rz), __float2bfloat16(rw));
    Hi[idx] = Hh; Lo[idx] = Ll;
}

// ---------------------------------------------------------------------------
// Prep: W [K,N] fp32 -> W^T [N,K] bf16 (hi,lo). 32x32 tiles, block (32,8).
// ---------------------------------------------------------------------------
__global__ void prep_w_kernel(const float* __restrict__ W,
                              __nv_bfloat16* __restrict__ Whi,
                              __nv_bfloat16* __restrict__ Wlo, int K, int N)
{
    __shared__ float t[32][33];
    int nb = blockIdx.x * 32, kb = blockIdx.y * 32;
    int tx = threadIdx.x, ty = threadIdx.y;
    #pragma unroll
    for (int i = 0; i < 4; i++) {
        int k = kb + ty + i * 8;
        t[ty + i * 8][tx] = W[(size_t)k * N + nb + tx];
    }
    __syncthreads();
    #pragma unroll
    for (int i = 0; i < 4; i++) {
        int n = nb + ty + i * 8;
        float v = t[tx][ty + i * 8];
        __nv_bfloat16 h = __float2bfloat16(v);
        __nv_bfloat16 l = __float2bfloat16(v - __bfloat162float(h));
        Whi[(size_t)n * K + kb + tx] = h;
        Wlo[(size_t)n * K + kb + tx] = l;
    }
}

// ---------------------------------------------------------------------------
// Split-bf16 GEMM on mma.sync: C[M,N] = A @ B^T, A hi/lo [M,K], B hi/lo [N,K].
// 128x128 CTA tile, BK=32, 8 warps (4m x 2n), warp tile 32x64 via m16n8k16.
// SMEM rows padded to 40 bf16 (80 B): conflict-free ldmatrix, 16B aligned.
// cp.async double-buffered pipeline (hardware-bounded waits; no spin loops).
// ---------------------------------------------------------------------------
#define PADROW 40
#define MAT_BYTES (128 * PADROW * 2)   // 10240
#define STAGE_B   (4 * MAT_BYTES)      // 40960
#define GEMM_SMEM (2 * STAGE_B)        // 81920

__global__ __launch_bounds__(256) void mma_gemm_kernel(
    const __nv_bfloat16* __restrict__ Ahi, const __nv_bfloat16* __restrict__ Alo,
    const __nv_bfloat16* __restrict__ Bhi, const __nv_bfloat16* __restrict__ Blo,
    float* __restrict__ Cc, int M, int N, int K)
{
    extern __shared__ char smem[];
    const uint32_t sb = smem_u32(smem);
    const int tid  = threadIdx.x;
    const int wid  = tid >> 5, lane = tid & 31;
    const int wm   = wid & 3,  wn   = wid >> 2;       // 4 x 2 warps
    const int m0   = blockIdx.y * 128, n0 = blockIdx.x * 128;
    const int NC   = K / 32;

    // --- cp.async source/dest precompute (per thread: 8 x 16B per stage) ---
    const int r    = tid >> 1;          // 0..127 row within tile
    const int half = tid & 1;           // 0/1 -> 16-element (32B) half of BK=32
    const __nv_bfloat16* gsrc[4] = {
        Ahi + (size_t)(m0 + r) * K + half * 16,
        Alo + (size_t)(m0 + r) * K + half * 16,
        Bhi + (size_t)(n0 + r) * K + half * 16,
        Blo + (size_t)(n0 + r) * K + half * 16
    };
    const uint32_t sdst_base = r * (PADROW * 2) + half * 32;  // bytes within matrix

    float acc[2][8][4];
    #pragma unroll
    for (int ma = 0; ma < 2; ma++)
        #pragma unroll
        for (int na = 0; na < 8; na++)
            #pragma unroll
            for (int q = 0; q < 4; q++) acc[ma][na][q] = 0.f;

    // Issue stage for chunk c into buffer s
    auto issue = [&](int c, int s) {
        const int koff = c * 32;
        #pragma unroll
        for (int mtx = 0; mtx < 4; mtx++) {
            uint32_t sd = sb + s * STAGE_B + mtx * MAT_BYTES + sdst_base;
            const __nv_bfloat16* gs = gsrc[mtx] + koff;
            CP_ASYNC16(sd,      gs);
            CP_ASYNC16(sd + 16, gs + 8);
        }
    };

    issue(0, 0); CP_COMMIT();

    for (int c = 0; c < NC; c++) {
        const int s = c & 1;
        if (c + 1 < NC) { issue(c + 1, s ^ 1); CP_COMMIT(); CP_WAIT(1); }
        else            { CP_WAIT(0); }
        __syncthreads();

        const uint32_t mb = sb + s * STAGE_B;
        #pragma unroll
        for (int h = 0; h < 2; h++) {               // two k16 halves of BK=32
            // A fragments (hi & lo): 2 m-atoms of 16 rows
            uint32_t ah[2][4], al[2][4];
            #pragma unroll
            for (int ma = 0; ma < 2; ma++) {
                int row = wm * 32 + ma * 16 + (lane & 15);
                uint32_t off = row * (PADROW * 2) + h * 32 + (lane >> 4) * 16;
                LDSM4(ah[ma][0], ah[ma][1], ah[ma][2], ah[ma][3], mb + 0 * MAT_BYTES + off);
                LDSM4(al[ma][0], al[ma][1], al[ma][2], al[ma][3], mb + 1 * MAT_BYTES + off);
            }
            // B fragments (hi & lo): 8 n-atoms (4 x4-loads each)
            uint32_t bh[8][2], bl[8][2];
            #pragma unroll
            for (int p = 0; p < 4; p++) {
                int row = wn * 64 + p * 16 + (lane & 7) + ((lane >> 4) & 1) * 8;
                uint32_t off = row * (PADROW * 2) + h * 32 + ((lane >> 3) & 1) * 16;
                LDSM4(bh[2*p][0], bh[2*p][1], bh[2*p+1][0], bh[2*p+1][1],
                      mb + 2 * MAT_BYTES + off);
                LDSM4(bl[2*p][0], bl[2*p][1], bl[2*p+1][0], bl[2*p+1][1],
                      mb + 3 * MAT_BYTES + off);
            }
            // 2 x 8 atoms x 3 split products
            #pragma unroll
            for (int ma = 0; ma < 2; ma++)
                #pragma unroll
                for (int na = 0; na < 8; na++) {
                    MMA16816(acc[ma][na], ah[ma], bh[na]);
                    MMA16816(acc[ma][na], ah[ma], bl[na]);
                    MMA16816(acc[ma][na], al[ma], bh[na]);
                }
        }
        __syncthreads();
    }

    // Epilogue: fragment -> global fp32 (float2 stores)
    const int g  = lane >> 2;
    const int i2 = (lane & 3) * 2;
    #pragma unroll
    for (int ma = 0; ma < 2; ma++) {
        #pragma unroll
        for (int na = 0; na < 8; na++) {
            int row = m0 + wm * 32 + ma * 16 + g;
            int col = n0 + wn * 64 + na * 8 + i2;
            *(float2*)&Cc[(size_t)row * N + col] =
                make_float2(acc[ma][na][0], acc[ma][na][1]);
            *(float2*)&Cc[(size_t)(row + 8) * N + col] =
                make_float2(acc[ma][na][2], acc[ma][na][3]);
        }
    }
}

// ---------------------------------------------------------------------------
// Flash attention, fp32 SIMT (proven in R2). Epilogue writes bf16 hi/lo.
// ---------------------------------------------------------------------------
__global__ __launch_bounds__(256) void flash_kernel()
{
    __shared__ float Qt[64 * 64];
    __shared__ float KP[64 * 36];
    __shared__ float Vs[32 * 64];

    const int tid = threadIdx.x;
    const int tx  = tid & 15;
    const int ty  = tid >> 4;
    const int bh  = blockIdx.y;
    const int b   = bh >> 4, h = bh & 15;
    const int q0  = blockIdx.x * 64;

    const float* Kbase = g_kqv + (size_t)b * T_ * KQV_COLS + h * Dh_;
    const float* Qbase = Kbase + C_;
    const float* Vbase = Kbase + 2 * C_;

    #pragma unroll
    for (int it = 0; it < 4; it++) {
        int fid = tid + it * 256;
        int q   = fid >> 4;
        int dg  = (fid & 15) * 4;
        float4 v = *(const float4*)(Qbase + (size_t)(q0 + q) * KQV_COLS + dg);
        Qt[(dg + 0) * 64 + q] = v.x * 0.125f;
        Qt[(dg + 1) * 64 + q] = v.y * 0.125f;
        Qt[(dg + 2) * 64 + q] = v.z * 0.125f;
        Qt[(dg + 3) * 64 + q] = v.w * 0.125f;
    }

    float o[4][4];
    float mi[4], li[4];
    #pragma unroll
    for (int i = 0; i < 4; i++) {
        mi[i] = -1e30f; li[i] = 0.f;
        #pragma unroll
        for (int j = 0; j < 4; j++) o[i][j] = 0.f;
    }

    for (int t = 0; t < T_ / 32; t++) {
        const int j0 = t * 32;
        __syncthreads();

        #pragma unroll
        for (int it = 0; it < 2; it++) {
            int fid = tid + it * 256;
            int kr  = fid >> 4;
            int dg  = (fid & 15) * 4;
            float4 kv = *(const float4*)(Kbase + (size_t)(j0 + kr) * KQV_COLS + dg);
            KP[(dg + 0) * 36 + kr] = kv.x;
            KP[(dg + 1) * 36 + kr] = kv.y;
            KP[(dg + 2) * 36 + kr] = kv.z;
            KP[(dg + 3) * 36 + kr] = kv.w;
            float4 vv = *(const float4*)(Vbase + (size_t)(j0 + kr) * KQV_COLS + dg);
            *(float4*)&Vs[kr * 64 + dg] = vv;
        }
        __syncthreads();

        float s[4][2];
        #pragma unroll
        for (int i = 0; i < 4; i++) { s[i][0] = 0.f; s[i][1] = 0.f; }
        #pragma unroll 16
        for (int d = 0; d < 64; d++) {
            float4 a  = *(const float4*)&Qt[d * 64 + ty * 4];
            float2 bk = *(const float2*)&KP[d * 36 + tx * 2];
            s[0][0] += a.x * bk.x;  s[0][1] += a.x * bk.y;
            s[1][0] += a.y * bk.x;  s[1][1] += a.y * bk.y;
            s[2][0] += a.z * bk.x;  s[2][1] += a.z * bk.y;
            s[3][0] += a.w * bk.x;  s[3][1] += a.w * bk.y;
        }

        float p[4][2], sc4[4];
        #pragma unroll
        for (int i = 0; i < 4; i++) {
            float rm = fmaxf(s[i][0], s[i][1]);
            #pragma unroll
            for (int off = 8; off; off >>= 1)
                rm = fmaxf(rm, __shfl_xor_sync(0xffffffffu, rm, off));
            float mnew = fmaxf(mi[i], rm);
            float scl  = __expf(mi[i] - mnew);
            p[i][0] = __expf(s[i][0] - mnew);
            p[i][1] = __expf(s[i][1] - mnew);
            float rs = p[i][0] + p[i][1];
            #pragma unroll
            for (int off = 8; off; off >>= 1)
                rs += __shfl_xor_sync(0xffffffffu, rs, off);
            li[i] = li[i] * scl + rs;
            mi[i] = mnew;
            sc4[i] = scl;
        }
        __syncthreads();

        #pragma unroll
        for (int j = 0; j < 2; j++) {
            *(float4*)&KP[(tx * 2 + j) * 68 + ty * 4] =
                make_float4(p[0][j], p[1][j], p[2][j], p[3][j]);
        }
        #pragma unroll
        for (int i = 0; i < 4; i++)
            #pragma unroll
            for (int j = 0; j < 4; j++) o[i][j] *= sc4[i];
        __syncthreads();

        #pragma unroll 8
        for (int k = 0; k < 32; k++) {
            float4 pp = *(const float4*)&KP[k * 68 + ty * 4];
            float4 vv = *(const float4*)&Vs[k * 64 + tx * 4];
            o[0][0] += pp.x * vv.x; o[0][1] += pp.x * vv.y; o[0][2] += pp.x * vv.z; o[0][3] += pp.x * vv.w;
            o[1][0] += pp.y * vv.x; o[1][1] += pp.y * vv.y; o[1][2] += pp.y * vv.z; o[1][3] += pp.y * vv.w;
            o[2][0] += pp.z * vv.x; o[2][1] += pp.z * vv.y; o[2][2] += pp.z * vv.z; o[2][3] += pp.z * vv.w;
            o[3][0] += pp.w * vv.x; o[3][1] += pp.w * vv.y; o[3][2] += pp.w * vv.z; o[3][3] += pp.w * vv.w;
        }
    }

    // Epilogue: normalize, split to bf16 hi/lo, write (B*T, C), col = h*64+d
    const size_t obase = (size_t)b * T_ * C_ + h * Dh_;
    #pragma unroll
    for (int i = 0; i < 4; i++) {
        float inv = 1.0f / li[i];
        size_t off = obase + (size_t)(q0 + ty * 4 + i) * C_ + tx * 4;
        __nv_bfloat16 hh[4]; float rr[4];
        #pragma unroll
        for (int j = 0; j < 4; j++) {
            float v = o[i][j] * inv;
            hh[j] = __float2bfloat16(v);
            rr[j] = v - __bfloat162float(hh[j]);
        }
        uint2 Hh; Hh.x = pack_bf(hh[0], hh[1]); Hh.y = pack_bf(hh[2], hh[3]);
        uint2 Ll; Ll.x = pack_bf(__float2bfloat16(rr[0]), __float2bfloat16(rr[1]));
        Ll.y = pack_bf(__float2bfloat16(rr[2]), __float2bfloat16(rr[3]));
        *(uint2*)(g_ahi + off) = Hh;
        *(uint2*)(g_alo + off) = Ll;
    }
}

// ---------------------------------------------------------------------------
extern "C" void kernel_launch(void* const* d_in, const int* in_sizes, int n_in,
                              void* d_out, int out_size)
{
    const float* x     = (const float*)d_in[0];   // (4,2048,1024)
    const float* Wkqv  = (const float*)d_in[1];   // (1024,3072)
    const float* Wproj = (const float*)d_in[2];   // (1024,1024)
    float* out = (float*)d_out;

    static float* p_kqv = nullptr;
    static __nv_bfloat16 *p_xhi, *p_xlo, *p_wkhi, *p_wklo, *p_wphi, *p_wplo, *p_ahi, *p_alo;
    if (!p_kqv) {
        cudaGetSymbolAddress((void**)&p_kqv,  g_kqv);
        cudaGetSymbolAddress((void**)&p_xhi,  g_xhi);
        cudaGetSymbolAddress((void**)&p_xlo,  g_xlo);
        cudaGetSymbolAddress((void**)&p_wkhi, g_wkhi);
        cudaGetSymbolAddress((void**)&p_wklo, g_wklo);
        cudaGetSymbolAddress((void**)&p_wphi, g_wphi);
        cudaGetSymbolAddress((void**)&p_wplo, g_wplo);
        cudaGetSymbolAddress((void**)&p_ahi,  g_ahi);
        cudaGetSymbolAddress((void**)&p_alo,  g_alo);
        cudaFuncSetAttribute(mma_gemm_kernel,
                             cudaFuncAttributeMaxDynamicSharedMemorySize, GEMM_SMEM);
    }

    // 0) Split x into bf16 hi/lo; transpose+split weights to [N,K] bf16
    prep_a_kernel<<<(M_ * C_) / 4 / 256, 256>>>((const float4*)x, (uint2*)p_xhi, (uint2*)p_xlo);
    prep_w_kernel<<<dim3(KQV_COLS / 32, C_ / 32), dim3(32, 8)>>>(Wkqv, p_wkhi, p_wklo, C_, KQV_COLS);
    prep_w_kernel<<<dim3(C_ / 32, C_ / 32), dim3(32, 8)>>>(Wproj, p_wphi, p_wplo, C_, C_);

    // 1) KQV projection via mma.sync: (8192,1024) @ (1024,3072) -> fp32
    mma_gemm_kernel<<<dim3(KQV_COLS / 128, M_ / 128), 256, GEMM_SMEM>>>(
        p_xhi, p_xlo, p_wkhi, p_wklo, p_kqv, M_, KQV_COLS, C_);

    // 2) Flash attention (fp32 SIMT), writes bf16 hi/lo attention output
    flash_kernel<<<dim3(T_ / 64, B_ * H_), 256>>>();

    // 3) Output projection via mma.sync: (8192,1024) @ (1024,1024) -> out fp32
    mma_gemm_kernel<<<dim3(C_ / 128, M_ / 128), 256, GEMM_SMEM>>>(
        p_ahi, p_alo, p_wphi, p_wplo, out, M_, C_, C_);
}

// round 7
// speedup vs baseline: 2.9507x; 2.1422x over previous
#include <cuda_runtime.h>
#include <cuda_bf16.h>
#include <cstdint>
#include <math.h>

#define B_  4
#define T_  2048
#define C_  1024
#define H_  16
#define Dh_ 64
#define KQV_COLS (3 * C_)   // 3072
#define M_  (B_ * T_)       // 8192

static_assert(Dh_ == 64 && H_ * Dh_ == C_, "head geometry");

// ---------------------------------------------------------------------------
// Device scratch
// ---------------------------------------------------------------------------
__device__ __align__(16) __nv_bfloat16 g_kqvhi[(size_t)M_ * KQV_COLS];
__device__ __align__(16) __nv_bfloat16 g_kqvlo[(size_t)M_ * KQV_COLS];
__device__ __align__(16) __nv_bfloat16 g_xhi [(size_t)M_ * C_];
__device__ __align__(16) __nv_bfloat16 g_xlo [(size_t)M_ * C_];
__device__ __align__(16) __nv_bfloat16 g_wkhi[(size_t)KQV_COLS * C_]; // [N,K]
__device__ __align__(16) __nv_bfloat16 g_wklo[(size_t)KQV_COLS * C_];
__device__ __align__(16) __nv_bfloat16 g_wphi[(size_t)C_ * C_];       // [N,K]
__device__ __align__(16) __nv_bfloat16 g_wplo[(size_t)C_ * C_];
__device__ __align__(16) __nv_bfloat16 g_ahi [(size_t)M_ * C_];
__device__ __align__(16) __nv_bfloat16 g_alo [(size_t)M_ * C_];

// ---------------------------------------------------------------------------
// PTX helpers (compute_103-legal: ldmatrix / mma.sync / cp.async)
// ---------------------------------------------------------------------------
__device__ __forceinline__ uint32_t smem_u32(const void* p) {
    uint32_t a;
    asm("{ .reg .u64 t; cvta.to.shared.u64 t, %1; cvt.u32.u64 %0, t; }" : "=r"(a) : "l"(p));
    return a;
}
#define LDSM4(r0, r1, r2, r3, addr) \
    asm volatile("ldmatrix.sync.aligned.m8n8.x4.shared.b16 {%0,%1,%2,%3}, [%4];" \
        : "=r"(r0), "=r"(r1), "=r"(r2), "=r"(r3) : "r"(addr))
#define LDSM4T(r0, r1, r2, r3, addr) \
    asm volatile("ldmatrix.sync.aligned.m8n8.x4.trans.shared.b16 {%0,%1,%2,%3}, [%4];" \
        : "=r"(r0), "=r"(r1), "=r"(r2), "=r"(r3) : "r"(addr))
#define MMA16816(d, a, b) \
    asm volatile("mma.sync.aligned.m16n8k16.row.col.f32.bf16.bf16.f32 " \
        "{%0,%1,%2,%3}, {%4,%5,%6,%7}, {%8,%9}, {%0,%1,%2,%3};" \
        : "+f"((d)[0]), "+f"((d)[1]), "+f"((d)[2]), "+f"((d)[3]) \
        : "r"((a)[0]), "r"((a)[1]), "r"((a)[2]), "r"((a)[3]), \
          "r"((b)[0]), "r"((b)[1]))
#define CP_ASYNC16(sdst, gsrc) \
    asm volatile("cp.async.cg.shared.global [%0], [%1], 16;" :: "r"(sdst), "l"(gsrc))
#define CP_COMMIT() asm volatile("cp.async.commit_group;" ::: "memory")
#define CP_WAIT(n)  asm volatile("cp.async.wait_group %0;" :: "n"(n) : "memory")

__device__ __forceinline__ uint32_t pack_bf(__nv_bfloat16 a, __nv_bfloat16 b) {
    return ((uint32_t)__bfloat16_as_ushort(b) << 16) | (uint32_t)__bfloat16_as_ushort(a);
}
__device__ __forceinline__ void split2(float v0, float v1, uint32_t& hi, uint32_t& lo) {
    __nv_bfloat16 h0 = __float2bfloat16(v0), h1 = __float2bfloat16(v1);
    hi = pack_bf(h0, h1);
    lo = pack_bf(__float2bfloat16(v0 - __bfloat162float(h0)),
                 __float2bfloat16(v1 - __bfloat162float(h1)));
}

// ---------------------------------------------------------------------------
// Prep kernels (unchanged from R6)
// ---------------------------------------------------------------------------
__global__ __launch_bounds__(256) void prep_a_kernel(
    const float4* __restrict__ X, uint2* __restrict__ Hi, uint2* __restrict__ Lo)
{
    int idx = blockIdx.x * 256 + threadIdx.x;
    float4 v = X[idx];
    uint32_t h0, l0, h1, l1;
    split2(v.x, v.y, h0, l0);
    split2(v.z, v.w, h1, l1);
    Hi[idx] = make_uint2(h0, h1); Lo[idx] = make_uint2(l0, l1);
}

__global__ void prep_w_kernel(const float* __restrict__ W,
                              __nv_bfloat16* __restrict__ Whi,
                              __nv_bfloat16* __restrict__ Wlo, int K, int N)
{
    __shared__ float t[32][33];
    int nb = blockIdx.x * 32, kb = blockIdx.y * 32;
    int tx = threadIdx.x, ty = threadIdx.y;
    #pragma unroll
    for (int i = 0; i < 4; i++) {
        int k = kb + ty + i * 8;
        t[ty + i * 8][tx] = W[(size_t)k * N + nb + tx];
    }
    __syncthreads();
    #pragma unroll
    for (int i = 0; i < 4; i++) {
        int n = nb + ty + i * 8;
        float v = t[tx][ty + i * 8];
        __nv_bfloat16 h = __float2bfloat16(v);
        Whi[(size_t)n * K + kb + tx] = h;
        Wlo[(size_t)n * K + kb + tx] = __float2bfloat16(v - __bfloat162float(h));
    }
}

// ---------------------------------------------------------------------------
// Split-bf16 GEMM on mma.sync (proven R6). Epilogue mode:
//   Chi==nullptr -> fp32 to Cc;  else -> split bf16 hi/lo to Chi/Clo.
// ---------------------------------------------------------------------------
#define PADROW 40
#define MAT_BYTES (128 * PADROW * 2)
#define STAGE_B   (4 * MAT_BYTES)
#define GEMM_SMEM (2 * STAGE_B)

__global__ __launch_bounds__(256) void mma_gemm_kernel(
    const __nv_bfloat16* __restrict__ Ahi, const __nv_bfloat16* __restrict__ Alo,
    const __nv_bfloat16* __restrict__ Bhi, const __nv_bfloat16* __restrict__ Blo,
    float* __restrict__ Cc, __nv_bfloat16* __restrict__ Chi,
    __nv_bfloat16* __restrict__ Clo, int M, int N, int K)
{
    extern __shared__ char smem[];
    const uint32_t sb = smem_u32(smem);
    const int tid  = threadIdx.x;
    const int wid  = tid >> 5, lane = tid & 31;
    const int wm   = wid & 3,  wn   = wid >> 2;
    const int m0   = blockIdx.y * 128, n0 = blockIdx.x * 128;
    const int NC   = K / 32;

    const int r    = tid >> 1;
    const int half = tid & 1;
    const __nv_bfloat16* gsrc[4] = {
        Ahi + (size_t)(m0 + r) * K + half * 16,
        Alo + (size_t)(m0 + r) * K + half * 16,
        Bhi + (size_t)(n0 + r) * K + half * 16,
        Blo + (size_t)(n0 + r) * K + half * 16
    };
    const uint32_t sdst_base = r * (PADROW * 2) + half * 32;

    float acc[2][8][4];
    #pragma unroll
    for (int ma = 0; ma < 2; ma++)
        #pragma unroll
        for (int na = 0; na < 8; na++)
            #pragma unroll
            for (int q = 0; q < 4; q++) acc[ma][na][q] = 0.f;

    auto issue = [&](int c, int s) {
        const int koff = c * 32;
        #pragma unroll
        for (int mtx = 0; mtx < 4; mtx++) {
            uint32_t sd = sb + s * STAGE_B + mtx * MAT_BYTES + sdst_base;
            const __nv_bfloat16* gs = gsrc[mtx] + koff;
            CP_ASYNC16(sd,      gs);
            CP_ASYNC16(sd + 16, gs + 8);
        }
    };

    issue(0, 0); CP_COMMIT();

    for (int c = 0; c < NC; c++) {
        const int s = c & 1;
        if (c + 1 < NC) { issue(c + 1, s ^ 1); CP_COMMIT(); CP_WAIT(1); }
        else            { CP_WAIT(0); }
        __syncthreads();

        const uint32_t mb = sb + s * STAGE_B;
        #pragma unroll
        for (int h = 0; h < 2; h++) {
            uint32_t ah[2][4], al[2][4];
            #pragma unroll
            for (int ma = 0; ma < 2; ma++) {
                int row = wm * 32 + ma * 16 + (lane & 15);
                uint32_t off = row * (PADROW * 2) + h * 32 + (lane >> 4) * 16;
                LDSM4(ah[ma][0], ah[ma][1], ah[ma][2], ah[ma][3], mb + 0 * MAT_BYTES + off);
                LDSM4(al[ma][0], al[ma][1], al[ma][2], al[ma][3], mb + 1 * MAT_BYTES + off);
            }
            uint32_t bh[8][2], bl[8][2];
            #pragma unroll
            for (int p = 0; p < 4; p++) {
                int row = wn * 64 + p * 16 + (lane & 7) + ((lane >> 4) & 1) * 8;
                uint32_t off = row * (PADROW * 2) + h * 32 + ((lane >> 3) & 1) * 16;
                LDSM4(bh[2*p][0], bh[2*p][1], bh[2*p+1][0], bh[2*p+1][1],
                      mb + 2 * MAT_BYTES + off);
                LDSM4(bl[2*p][0], bl[2*p][1], bl[2*p+1][0], bl[2*p+1][1],
                      mb + 3 * MAT_BYTES + off);
            }
            #pragma unroll
            for (int ma = 0; ma < 2; ma++)
                #pragma unroll
                for (int na = 0; na < 8; na++) {
                    MMA16816(acc[ma][na], ah[ma], bh[na]);
                    MMA16816(acc[ma][na], ah[ma], bl[na]);
                    MMA16816(acc[ma][na], al[ma], bh[na]);
                }
        }
        __syncthreads();
    }

    const int g  = lane >> 2;
    const int i2 = (lane & 3) * 2;
    #pragma unroll
    for (int ma = 0; ma < 2; ma++) {
        #pragma unroll
        for (int na = 0; na < 8; na++) {
            int row = m0 + wm * 32 + ma * 16 + g;
            int col = n0 + wn * 64 + na * 8 + i2;
            if (Chi) {
                uint32_t h0, l0, h1, l1;
                split2(acc[ma][na][0], acc[ma][na][1], h0, l0);
                split2(acc[ma][na][2], acc[ma][na][3], h1, l1);
                *(uint32_t*)&Chi[(size_t)row * N + col] = h0;
                *(uint32_t*)&Clo[(size_t)row * N + col] = l0;
                *(uint32_t*)&Chi[(size_t)(row + 8) * N + col] = h1;
                *(uint32_t*)&Clo[(size_t)(row + 8) * N + col] = l1;
            } else {
                *(float2*)&Cc[(size_t)row * N + col] =
                    make_float2(acc[ma][na][0], acc[ma][na][1]);
                *(float2*)&Cc[(size_t)(row + 8) * N + col] =
                    make_float2(acc[ma][na][2], acc[ma][na][3]);
            }
        }
    }
}

// ---------------------------------------------------------------------------
// Flash attention on mma.sync. CTA = 128 queries of one (b,h); key tiles 64.
// Q hi/lo persistent register A-frags; K/V hi/lo double-buffered cp.async.
// S = 3-MMA split QK^T; softmax in registers; P hi/lo built in-register;
// O += 3-MMA split P@V with V B-frags via ldmatrix.trans.
// 8 warps; warp w owns q rows [w*16, w*16+16).
// ---------------------------------------------------------------------------
#define FPAD   72                    // padded row (bf16) -> 144 B, odd 16B units
#define FROWB  (FPAD * 2)            // 144
#define FMAT   (64 * FROWB)          // 9216 B per matrix per stage
#define FSTAGE (4 * FMAT)            // khi, klo, vhi, vlo
#define FLASH_SMEM (2 * FSTAGE)      // 73728
#define QMATB  (128 * FROWB)         // 18432 (Q staging, overlaps stage area)

__global__ __launch_bounds__(256) void flash_mma_kernel()
{
    extern __shared__ char fsm[];
    const uint32_t sb = smem_u32(fsm);
    const int tid = threadIdx.x, wid = tid >> 5, lane = tid & 31;
    const int bh = blockIdx.y, b = bh >> 4, h = bh & 15;
    const int q0 = blockIdx.x * 128;

    const __nv_bfloat16* khi = g_kqvhi + (size_t)b * T_ * KQV_COLS + h * Dh_;
    const __nv_bfloat16* klo = g_kqvlo + (size_t)b * T_ * KQV_COLS + h * Dh_;

    // ---- Prologue: stage Q (hi at 0, lo at QMATB), build persistent frags ----
    #pragma unroll
    for (int it = 0; it < 2; it++) {
        int u   = tid + it * 256;          // 0..511
        int row = u >> 2, c4 = u & 3;
        size_t go = (size_t)(q0 + row) * KQV_COLS + C_ + c4 * 16;  // q at s=1
        uint32_t d0 = sb + row * FROWB + c4 * 32;
        CP_ASYNC16(d0,          khi + go);
        CP_ASYNC16(d0 + 16,     khi + go + 8);
        CP_ASYNC16(d0 + QMATB,      klo + go);
        CP_ASYNC16(d0 + QMATB + 16, klo + go + 8);
    }
    CP_COMMIT(); CP_WAIT(0); __syncthreads();

    uint32_t qh[4][4], ql[4][4];
    {
        int row = wid * 16 + (lane & 15);
        #pragma unroll
        for (int ks = 0; ks < 4; ks++) {
            uint32_t off = row * FROWB + ks * 32 + (lane >> 4) * 16;
            LDSM4(qh[ks][0], qh[ks][1], qh[ks][2], qh[ks][3], sb + off);
            LDSM4(ql[ks][0], ql[ks][1], ql[ks][2], ql[ks][3], sb + QMATB + off);
        }
    }
    __syncthreads();   // Q staging area now reusable as stage buffers

    // KV stage issue: 64 rows x 4 matrices, 8 x 16B per thread
    auto issueKV = [&](int t, int s) {
        int row = tid >> 2, c4 = tid & 3;
        size_t go = (size_t)(t * 64 + row) * KQV_COLS + c4 * 16;
        uint32_t d = sb + s * FSTAGE + row * FROWB + c4 * 32;
        CP_ASYNC16(d + 0 * FMAT,      khi + go);            // K hi (s=0)
        CP_ASYNC16(d + 0 * FMAT + 16, khi + go + 8);
        CP_ASYNC16(d + 1 * FMAT,      klo + go);            // K lo
        CP_ASYNC16(d + 1 * FMAT + 16, klo + go + 8);
        CP_ASYNC16(d + 2 * FMAT,      khi + 2 * C_ + go);   // V hi (s=2)
        CP_ASYNC16(d + 2 * FMAT + 16, khi + 2 * C_ + go + 8);
        CP_ASYNC16(d + 3 * FMAT,      klo + 2 * C_ + go);   // V lo
        CP_ASYNC16(d + 3 * FMAT + 16, klo + 2 * C_ + go + 8);
    };

    float o[8][4];
    #pragma unroll
    for (int na = 0; na < 8; na++)
        #pragma unroll
        for (int q = 0; q < 4; q++) o[na][q] = 0.f;
    float mi[2] = {-1e30f, -1e30f}, li[2] = {0.f, 0.f};

    issueKV(0, 0); CP_COMMIT();

    const int NT = T_ / 64;   // 32
    for (int t = 0; t < NT; t++) {
        const int s = t & 1;
        if (t + 1 < NT) { issueKV(t + 1, s ^ 1); CP_COMMIT(); CP_WAIT(1); }
        else            { CP_WAIT(0); }
        __syncthreads();

        const uint32_t khm = sb + s * FSTAGE;
        const uint32_t klm = khm + FMAT;
        const uint32_t vhm = khm + 2 * FMAT;
        const uint32_t vlm = khm + 3 * FMAT;

        // ---- S = Q K^T (3-way split) ----
        float sc[8][4];
        #pragma unroll
        for (int na = 0; na < 8; na++)
            #pragma unroll
            for (int q = 0; q < 4; q++) sc[na][q] = 0.f;

        #pragma unroll
        for (int ks = 0; ks < 4; ks++) {
            #pragma unroll
            for (int p = 0; p < 4; p++) {
                int brow = p * 16 + (lane & 7) + ((lane >> 4) & 1) * 8;
                uint32_t boff = brow * FROWB + ks * 32 + ((lane >> 3) & 1) * 16;
                uint32_t b0h, b1h, b2h, b3h, b0l, b1l, b2l, b3l;
                LDSM4(b0h, b1h, b2h, b3h, khm + boff);
                LDSM4(b0l, b1l, b2l, b3l, klm + boff);
                uint32_t Bh0[2] = {b0h, b1h}, Bh1[2] = {b2h, b3h};
                uint32_t Bl0[2] = {b0l, b1l}, Bl1[2] = {b2l, b3l};
                MMA16816(sc[2*p],   qh[ks], Bh0);
                MMA16816(sc[2*p],   qh[ks], Bl0);
                MMA16816(sc[2*p],   ql[ks], Bh0);
                MMA16816(sc[2*p+1], qh[ks], Bh1);
                MMA16816(sc[2*p+1], qh[ks], Bl1);
                MMA16816(sc[2*p+1], ql[ks], Bh1);
            }
        }
        #pragma unroll
        for (int na = 0; na < 8; na++)
            #pragma unroll
            for (int q = 0; q < 4; q++) sc[na][q] *= 0.125f;   // dk

        // ---- online softmax (rows g -> c0,c1 ; g+8 -> c2,c3) ----
        float scl[2];
        #pragma unroll
        for (int rr = 0; rr < 2; rr++) {
            float rm = -1e30f;
            #pragma unroll
            for (int na = 0; na < 8; na++)
                rm = fmaxf(rm, fmaxf(sc[na][2*rr], sc[na][2*rr+1]));
            rm = fmaxf(rm, __shfl_xor_sync(0xffffffffu, rm, 1));
            rm = fmaxf(rm, __shfl_xor_sync(0xffffffffu, rm, 2));
            float mnew = fmaxf(mi[rr], rm);
            scl[rr] = __expf(mi[rr] - mnew);
            float rs = 0.f;
            #pragma unroll
            for (int na = 0; na < 8; na++) {
                sc[na][2*rr]   = __expf(sc[na][2*rr]   - mnew);
                sc[na][2*rr+1] = __expf(sc[na][2*rr+1] - mnew);
                rs += sc[na][2*rr] + sc[na][2*rr+1];
            }
            rs += __shfl_xor_sync(0xffffffffu, rs, 1);
            rs += __shfl_xor_sync(0xffffffffu, rs, 2);
            li[rr] = li[rr] * scl[rr] + rs;
            mi[rr] = mnew;
        }
        #pragma unroll
        for (int na = 0; na < 8; na++) {
            o[na][0] *= scl[0]; o[na][1] *= scl[0];
            o[na][2] *= scl[1]; o[na][3] *= scl[1];
        }

        // ---- O += P V (3-way split); P frags from sc in-register ----
        #pragma unroll
        for (int ks = 0; ks < 4; ks++) {
            uint32_t pah[4], pal[4];
            split2(sc[2*ks  ][0], sc[2*ks  ][1], pah[0], pal[0]);
            split2(sc[2*ks  ][2], sc[2*ks  ][3], pah[1], pal[1]);
            split2(sc[2*ks+1][0], sc[2*ks+1][1], pah[2], pal[2]);
            split2(sc[2*ks+1][2], sc[2*ks+1][3], pah[3], pal[3]);
            #pragma unroll
            for (int nb = 0; nb < 4; nb++) {
                int vrow = ks * 16 + (lane & 7) + ((lane >> 3) & 1) * 8;
                uint32_t voff = vrow * FROWB + (nb * 16 + (lane >> 4) * 8) * 2;
                uint32_t v0h, v1h, v2h, v3h, v0l, v1l, v2l, v3l;
                LDSM4T(v0h, v1h, v2h, v3h, vhm + voff);
                LDSM4T(v0l, v1l, v2l, v3l, vlm + voff);
                uint32_t Vh0[2] = {v0h, v1h}, Vh1[2] = {v2h, v3h};
                uint32_t Vl0[2] = {v0l, v1l}, Vl1[2] = {v2l, v3l};
                MMA16816(o[2*nb],   pah, Vh0);
                MMA16816(o[2*nb],   pah, Vl0);
                MMA16816(o[2*nb],   pal, Vh0);
                MMA16816(o[2*nb+1], pah, Vh1);
                MMA16816(o[2*nb+1], pah, Vl1);
                MMA16816(o[2*nb+1], pal, Vh1);
            }
        }
        __syncthreads();
    }

    // ---- Epilogue: normalize, split bf16 hi/lo to g_ahi/g_alo ----
    const float inv0 = 1.0f / li[0], inv1 = 1.0f / li[1];
    const int g  = lane >> 2;
    const int n2 = (lane & 3) * 2;
    const size_t row0 = (size_t)b * T_ + q0 + wid * 16 + g;
    #pragma unroll
    for (int na = 0; na < 8; na++) {
        int col = h * Dh_ + na * 8 + n2;
        uint32_t h0, l0, h1, l1;
        split2(o[na][0] * inv0, o[na][1] * inv0, h0, l0);
        split2(o[na][2] * inv1, o[na][3] * inv1, h1, l1);
        *(uint32_t*)&g_ahi[row0 * C_ + col] = h0;
        *(uint32_t*)&g_alo[row0 * C_ + col] = l0;
        *(uint32_t*)&g_ahi[(row0 + 8) * C_ + col] = h1;
        *(uint32_t*)&g_alo[(row0 + 8) * C_ + col] = l1;
    }
}

// ---------------------------------------------------------------------------
extern "C" void kernel_launch(void* const* d_in, const int* in_sizes, int n_in,
                              void* d_out, int out_size)
{
    const float* x     = (const float*)d_in[0];
    const float* Wkqv  = (const float*)d_in[1];
    const float* Wproj = (const float*)d_in[2];
    float* out = (float*)d_out;

    static __nv_bfloat16* p_kqvhi = nullptr;
    static __nv_bfloat16 *p_kqvlo, *p_xhi, *p_xlo, *p_wkhi, *p_wklo,
                         *p_wphi, *p_wplo, *p_ahi, *p_alo;
    if (!p_kqvhi) {
        cudaGetSymbolAddress((void**)&p_kqvhi, g_kqvhi);
        cudaGetSymbolAddress((void**)&p_kqvlo, g_kqvlo);
        cudaGetSymbolAddress((void**)&p_xhi,  g_xhi);
        cudaGetSymbolAddress((void**)&p_xlo,  g_xlo);
        cudaGetSymbolAddress((void**)&p_wkhi, g_wkhi);
        cudaGetSymbolAddress((void**)&p_wklo, g_wklo);
        cudaGetSymbolAddress((void**)&p_wphi, g_wphi);
        cudaGetSymbolAddress((void**)&p_wplo, g_wplo);
        cudaGetSymbolAddress((void**)&p_ahi,  g_ahi);
        cudaGetSymbolAddress((void**)&p_alo,  g_alo);
        cudaFuncSetAttribute(mma_gemm_kernel,
                             cudaFuncAttributeMaxDynamicSharedMemorySize, GEMM_SMEM);
        cudaFuncSetAttribute(flash_mma_kernel,
                             cudaFuncAttributeMaxDynamicSharedMemorySize, FLASH_SMEM);
    }

    prep_a_kernel<<<(M_ * C_) / 4 / 256, 256>>>((const float4*)x, (uint2*)p_xhi, (uint2*)p_xlo);
    prep_w_kernel<<<dim3(KQV_COLS / 32, C_ / 32), dim3(32, 8)>>>(Wkqv, p_wkhi, p_wklo, C_, KQV_COLS);
    prep_w_kernel<<<dim3(C_ / 32, C_ / 32), dim3(32, 8)>>>(Wproj, p_wphi, p_wplo, C_, C_);

    // 1) KQV projection -> bf16 hi/lo directly
    mma_gemm_kernel<<<dim3(KQV_COLS / 128, M_ / 128), 256, GEMM_SMEM>>>(
        p_xhi, p_xlo, p_wkhi, p_wklo, nullptr, p_kqvhi, p_kqvlo, M_, KQV_COLS, C_);

    // 2) Flash attention on tensor cores
    flash_mma_kernel<<<dim3(T_ / 128, B_ * H_), 256, FLASH_SMEM>>>();

    // 3) Output projection -> fp32 out
    mma_gemm_kernel<<<dim3(C_ / 128, M_ / 128), 256, GEMM_SMEM>>>(
        p_ahi, p_alo, p_wphi, p_wplo, out, nullptr, nullptr, M_, C_, C_);
}